// round 12
// baseline (speedup 1.0000x reference)
#include <cuda_runtime.h>
#include <cuda_bf16.h>
#include <cstdint>

// YOLOv1 loss — single kernel, R1's proven streaming structure (36.8us = the
// measured memory wall for this pattern) + ZERO-WAIT epilogue:
//   workers: 4x relaxed RED.ADD.F64 + red.release counter (fire-and-forget,
//            no return, no fence, no block wait — exits like R1 did)
//   block 6272: dedicated spinner — polls counter, fence.acquire, finalizes.

#define NCELL  (16384 * 7 * 7)       // 802816
#define BLK    128
#define TILE   128                   // cells per worker block
#define NTILE  (NCELL / TILE)        // 6272 worker blocks
#define TFL    (TILE * 30)           // floats per tensor per tile (3840)
#define TF4    (TFL / 4)             // float4 per tensor per tile (960)

__device__ double g_acc[4] = {0.0, 0.0, 0.0, 0.0};   // cls, conf, cwh, noobj
__device__ unsigned int g_count = 0;

__global__ __launch_bounds__(BLK) void yolo_fused(const float* __restrict__ P,
                                                  const float* __restrict__ T,
                                                  float* __restrict__ out)
{
    // ---------------- spinner block: finalize when all workers done --------
    if (blockIdx.x == NTILE) {
        if (threadIdx.x == 0) {
            unsigned int c;
            for (;;) {
                asm volatile("ld.global.cg.u32 %0, [%1];"
                             : "=r"(c) : "l"(&g_count) : "memory");
                if (c >= (unsigned int)NTILE) break;
                __nanosleep(256);
            }
            asm volatile("fence.acquire.gpu;" ::: "memory");
            const double a0 = __ldcg(&g_acc[0]);
            const double a1 = __ldcg(&g_acc[1]);
            const double a2 = __ldcg(&g_acc[2]);
            const double a3 = __ldcg(&g_acc[3]);
            const float cls = (float)(5.0 * a0);   // lambda_coord
            const float cnf = (float)(5.0 * a1);
            const float cwh = (float)(5.0 * a2);
            const float nob = (float)(0.5 * a3);   // lambda_noobj
            out[0] = cls;
            out[1] = cnf;
            out[2] = cwh;
            out[3] = nob + cls + cnf + cwh;        // total
            // reset for next graph replay (kernel boundary orders these)
            g_acc[0] = 0.0; g_acc[1] = 0.0; g_acc[2] = 0.0; g_acc[3] = 0.0;
            g_count = 0;
        }
        return;
    }

    // ---------------- worker blocks: exactly R1's streaming ----------------
    __shared__ float SP[TFL];
    __shared__ float ST[TFL];
    const int tid = threadIdx.x;
    const float CELL = 1.0f / 7.0f;

    const size_t base = (size_t)blockIdx.x * TFL;
    const float4* gp = (const float4*)(P + base);
    const float4* gt = (const float4*)(T + base);
    float4* sp4 = (float4*)SP;
    float4* st4 = (float4*)ST;
    #pragma unroll
    for (int i = 0; i < (TF4 + BLK - 1) / BLK; ++i) {
        int idx = tid + i * BLK;
        if (idx < TF4) { sp4[idx] = gp[idx]; st4[idx] = gt[idx]; }
    }
    __syncthreads();

    const float* p = SP + tid * 30;
    const float* t = ST + tid * 30;

    const float t0 = t[0], t1 = t[1], t2 = t[2], t3 = t[3], tc = t[4];

    // target corners — faithful to the reference's in-place bug:
    //   xy1 = xy*CELL - wh*0.5 ;  xy2 = xy1*CELL + wh*0.5
    const float twx = t2 * t2, twy = t3 * t3;
    const float tx1 = t0 * CELL - 0.5f * twx;
    const float ty1 = t1 * CELL - 0.5f * twy;
    const float tx2 = tx1 * CELL + 0.5f * twx;
    const float ty2 = ty1 * CELL + 0.5f * twy;
    const float area_t = (tx2 - tx1) * (ty2 - ty1);

    float iou0, iou1;
    #pragma unroll
    for (int b = 0; b < 2; ++b) {
        const float px = p[b * 5 + 0], py = p[b * 5 + 1];
        const float pw = p[b * 5 + 2], ph = p[b * 5 + 3];
        const float pwx = pw * pw, pwy = ph * ph;
        const float x1 = px * CELL - 0.5f * pwx;
        const float y1 = py * CELL - 0.5f * pwy;
        const float x2 = x1 * CELL + 0.5f * pwx;
        const float y2 = y1 * CELL + 0.5f * pwy;
        const float ltx = fmaxf(x1, tx1), lty = fmaxf(y1, ty1);
        const float rbx = fminf(x2, tx2), rby = fminf(y2, ty2);
        const float dx = fmaxf(rbx - ltx, 0.0f);
        const float dy = fmaxf(rby - lty, 0.0f);
        const float inter  = dx * dy;
        const float area_p = (x2 - x1) * (y2 - y1);
        const float v = inter / (area_p + area_t - inter);
        if (b == 0) iou0 = v; else iou1 = v;
    }
    const int b5 = (iou1 > iou0) ? 5 : 0;     // first max wins ties

    // argmax over t[10:30] — order-preserving tree (adjacent pairing keeps
    // index sets contiguous & ordered -> exact first-max semantics, depth 5)
    float av[10]; int ak[10];
    #pragma unroll
    for (int k = 0; k < 10; ++k) {
        const float a = t[10 + 2 * k], b = t[11 + 2 * k];
        const bool g = b > a;
        av[k] = g ? b : a;
        ak[k] = 10 + 2 * k + (g ? 1 : 0);
    }
    #pragma unroll
    for (int k = 0; k < 5; ++k) {
        const bool g = av[2 * k + 1] > av[2 * k];
        av[k] = g ? av[2 * k + 1] : av[2 * k];
        ak[k] = g ? ak[2 * k + 1] : ak[2 * k];
    }
    { const bool g = av[1] > av[0]; av[0] = g ? av[1] : av[0]; ak[0] = g ? ak[1] : ak[0]; }
    { const bool g = av[3] > av[2]; av[2] = g ? av[3] : av[2]; ak[2] = g ? ak[3] : ak[2]; }
    { const bool g = av[2] > av[0]; av[0] = g ? av[2] : av[0]; ak[0] = g ? ak[2] : ak[0]; }
    { const bool g = av[4] > av[0]; av[0] = g ? av[4] : av[0]; ak[0] = g ? ak[4] : ak[0]; }
    const int   kcol = ak[0];
    const float tmax = av[0];     // == t[kcol]

    const bool obj = (tc == 1.0f);
    const bool noo = (tc == 0.0f);

    const float dk = p[kcol]   - tmax;
    const float dc = p[b5 + 4] - t[b5 + 4];
    const float d0 = p[b5 + 0] - t[b5 + 0];
    const float d1 = p[b5 + 1] - t[b5 + 1];
    const float d2 = p[b5 + 2] - t[b5 + 2];
    const float d3 = p[b5 + 3] - t[b5 + 3];
    const float d4 = p[4] - tc;
    const float d9 = p[9] - t[9];

    float ax = 0.0f, ay = 0.0f, az = 0.0f, aw = 0.0f;
    if (obj) {
        ax = dk * dk;                                   // cls
        ay = dc * dc;                                   // conf
        az = d0 * d0 + d1 * d1 + d2 * d2 + d3 * d3;     // center+wh
    }
    if (noo) aw = d4 * d4 + d9 * d9;                    // noobj

    // ---- block reduce ----
    #pragma unroll
    for (int o = 16; o > 0; o >>= 1) {
        ax += __shfl_down_sync(0xffffffffu, ax, o);
        ay += __shfl_down_sync(0xffffffffu, ay, o);
        az += __shfl_down_sync(0xffffffffu, az, o);
        aw += __shfl_down_sync(0xffffffffu, aw, o);
    }
    __shared__ float4 wsum[BLK / 32];
    if ((tid & 31) == 0) wsum[tid >> 5] = make_float4(ax, ay, az, aw);
    __syncthreads();
    if (tid == 0) {
        float4 sv = wsum[0];
        #pragma unroll
        for (int w = 1; w < BLK / 32; ++w) {
            sv.x += wsum[w].x; sv.y += wsum[w].y;
            sv.z += wsum[w].z; sv.w += wsum[w].w;
        }
        // fire-and-forget: relaxed fp64 REDs, then RELEASE counter tick.
        // No return value, no fence, no wait — block exits immediately.
        atomicAdd(&g_acc[0], (double)sv.x);
        atomicAdd(&g_acc[1], (double)sv.y);
        atomicAdd(&g_acc[2], (double)sv.z);
        atomicAdd(&g_acc[3], (double)sv.w);
        asm volatile("red.release.gpu.global.add.u32 [%0], 1;"
                     :: "l"(&g_count) : "memory");
    }
    // no trailing syncthreads — warps retire as they arrive, like R1
}

extern "C" void kernel_launch(void* const* d_in, const int* in_sizes, int n_in,
                              void* d_out, int out_size)
{
    const float* P = (const float*)d_in[0];   // predictions [B,S,S,30] fp32
    const float* T = (const float*)d_in[1];   // targets     [B,S,S,30] fp32
    float* out = (float*)d_out;               // [cls, conf, center+wh, total]

    yolo_fused<<<NTILE + 1, BLK>>>(P, T, out);
}

// round 13
// speedup vs baseline: 1.1537x; 1.1537x over previous
#include <cuda_runtime.h>
#include <cuda_bf16.h>
#include <cstdint>

// YOLOv1 loss — persistent 64-thread blocks, TILE=64 double-buffered cp.async
// (2 x 15.36KB stages = 30.7KB -> still 7 blocks/SM, but demand is continuous),
// balanced contiguous tile ranges per block, R8's proven last-block epilogue.

#define NCELL  (16384 * 7 * 7)       // 802816
#define BLK    64
#define BPSM   7
#define GRID   (148 * BPSM)          // 1036 persistent blocks
#define TILE   64                    // cells per tile
#define NTILE  (NCELL / TILE)        // 12544
#define TFL    (TILE * 30)           // floats per tensor per tile (1920)
#define TF4    (TFL / 4)             // float4 per tensor per tile (480)
#define STGF   (2 * TFL)             // floats per stage [P|T] (3840)
#define NLD    15                    // cp.asyncs per thread per tile (2*TF4/BLK)

__device__ float4 g_part[GRID];
__device__ unsigned int g_count = 0;

__device__ __forceinline__ void cp16(float4* dst_smem, const float4* src_gmem) {
    unsigned int d = (unsigned int)__cvta_generic_to_shared(dst_smem);
    asm volatile("cp.async.cg.shared.global [%0], [%1], 16;\n" :: "r"(d), "l"(src_gmem));
}
__device__ __forceinline__ void cp_commit() { asm volatile("cp.async.commit_group;\n"); }
__device__ __forceinline__ void cp_wait1()  { asm volatile("cp.async.wait_group 1;\n"); }

__device__ __forceinline__ void prefetch_tile(float* stage, int tile,
                                              const float* P, const float* T, int tid)
{
    const float4* gp = (const float4*)(P + (size_t)tile * TFL);
    const float4* gt = (const float4*)(T + (size_t)tile * TFL);
    float4* d = (float4*)stage;
    #pragma unroll
    for (int i = 0; i < NLD; ++i) {
        const int idx = tid + i * BLK;            // 0..959
        const float4* src = (idx < TF4) ? (gp + idx) : (gt + (idx - TF4));
        cp16(d + idx, src);
    }
}

__global__ __launch_bounds__(BLK, BPSM)
void yolo_fused(const float* __restrict__ P,
                const float* __restrict__ T,
                float* __restrict__ out)
{
    __shared__ float stagebuf[2 * STGF];    // 2 stages x 15360 B = 30720 B
    const int tid = threadIdx.x;
    const int bid = blockIdx.x;
    const float CELL = 1.0f / 7.0f;

    // balanced contiguous tile range: extras spread uniformly across bids/SMs
    const int ts = (int)(((long long)bid * NTILE) / GRID);
    const int te = (int)(((long long)(bid + 1) * NTILE) / GRID);

    float ax = 0.0f, ay = 0.0f, az = 0.0f, aw = 0.0f;

    int s = 0;
    prefetch_tile(stagebuf, ts, P, T, tid);   // te > ts always (NTILE > GRID)
    cp_commit();

    for (int tile = ts; tile < te; ++tile) {
        if (tile + 1 < te) prefetch_tile(stagebuf + (s ^ 1) * STGF, tile + 1, P, T, tid);
        cp_commit();                          // (possibly empty) group
        cp_wait1();                           // current tile's stage complete
        __syncthreads();

        const float* p = stagebuf + s * STGF + tid * 30;
        const float* t = p + TFL;

        const float t0 = t[0], t1 = t[1], t2 = t[2], t3 = t[3], tc = t[4];

        // target corners — faithful to the reference's in-place bug:
        //   xy1 = xy*CELL - wh*0.5 ;  xy2 = xy1*CELL + wh*0.5
        const float twx = t2 * t2, twy = t3 * t3;
        const float tx1 = t0 * CELL - 0.5f * twx;
        const float ty1 = t1 * CELL - 0.5f * twy;
        const float tx2 = tx1 * CELL + 0.5f * twx;
        const float ty2 = ty1 * CELL + 0.5f * twy;
        const float area_t = (tx2 - tx1) * (ty2 - ty1);

        float iou0, iou1;
        #pragma unroll
        for (int b = 0; b < 2; ++b) {
            const float px = p[b * 5 + 0], py = p[b * 5 + 1];
            const float pw = p[b * 5 + 2], ph = p[b * 5 + 3];
            const float pwx = pw * pw, pwy = ph * ph;
            const float x1 = px * CELL - 0.5f * pwx;
            const float y1 = py * CELL - 0.5f * pwy;
            const float x2 = x1 * CELL + 0.5f * pwx;
            const float y2 = y1 * CELL + 0.5f * pwy;
            const float ltx = fmaxf(x1, tx1), lty = fmaxf(y1, ty1);
            const float rbx = fminf(x2, tx2), rby = fminf(y2, ty2);
            const float dx = fmaxf(rbx - ltx, 0.0f);
            const float dy = fmaxf(rby - lty, 0.0f);
            const float inter  = dx * dy;
            const float area_p = (x2 - x1) * (y2 - y1);
            const float v = inter / (area_p + area_t - inter);
            if (b == 0) iou0 = v; else iou1 = v;
        }
        const int b5 = (iou1 > iou0) ? 5 : 0;     // first max wins ties

        // argmax over t[10:30] — order-preserving tree (exact first-max, depth 5)
        float av[10]; int ak[10];
        #pragma unroll
        for (int k = 0; k < 10; ++k) {
            const float a = t[10 + 2 * k], b = t[11 + 2 * k];
            const bool g = b > a;
            av[k] = g ? b : a;
            ak[k] = 10 + 2 * k + (g ? 1 : 0);
        }
        #pragma unroll
        for (int k = 0; k < 5; ++k) {
            const bool g = av[2 * k + 1] > av[2 * k];
            av[k] = g ? av[2 * k + 1] : av[2 * k];
            ak[k] = g ? ak[2 * k + 1] : ak[2 * k];
        }
        { const bool g = av[1] > av[0]; av[0] = g ? av[1] : av[0]; ak[0] = g ? ak[1] : ak[0]; }
        { const bool g = av[3] > av[2]; av[2] = g ? av[3] : av[2]; ak[2] = g ? ak[3] : ak[2]; }
        { const bool g = av[2] > av[0]; av[0] = g ? av[2] : av[0]; ak[0] = g ? ak[2] : ak[0]; }
        { const bool g = av[4] > av[0]; av[0] = g ? av[4] : av[0]; ak[0] = g ? ak[4] : ak[0]; }
        const int   kcol = ak[0];
        const float tmax = av[0];     // == t[kcol]

        const bool obj = (tc == 1.0f);
        const bool noo = (tc == 0.0f);

        const float dk = p[kcol]   - tmax;
        const float dc = p[b5 + 4] - t[b5 + 4];
        const float d0 = p[b5 + 0] - t[b5 + 0];
        const float d1 = p[b5 + 1] - t[b5 + 1];
        const float d2 = p[b5 + 2] - t[b5 + 2];
        const float d3 = p[b5 + 3] - t[b5 + 3];
        const float d4 = p[4] - tc;
        const float d9 = p[9] - t[9];

        if (obj) {
            ax += dk * dk;                                   // cls
            ay += dc * dc;                                   // conf
            az += d0 * d0 + d1 * d1 + d2 * d2 + d3 * d3;     // center+wh
        }
        if (noo) aw += d4 * d4 + d9 * d9;                    // noobj

        __syncthreads();              // reads done before stage s is reused
        s ^= 1;
    }

    // ---- block reduce (2 warps) ----
    #pragma unroll
    for (int o = 16; o > 0; o >>= 1) {
        ax += __shfl_down_sync(0xffffffffu, ax, o);
        ay += __shfl_down_sync(0xffffffffu, ay, o);
        az += __shfl_down_sync(0xffffffffu, az, o);
        aw += __shfl_down_sync(0xffffffffu, aw, o);
    }
    __shared__ float4 wsum[BLK / 32];
    __shared__ bool s_last;
    if ((tid & 31) == 0) wsum[tid >> 5] = make_float4(ax, ay, az, aw);
    __syncthreads();
    if (tid == 0) {
        float4 sv = wsum[0];
        sv.x += wsum[1].x; sv.y += wsum[1].y;
        sv.z += wsum[1].z; sv.w += wsum[1].w;
        __stcg(&g_part[bid], sv);
        __threadfence();
        unsigned int prev = atomicAdd(&g_count, 1u);
        s_last = (prev == (unsigned int)(GRID - 1));
    }
    __syncthreads();
    if (!s_last) return;

    // ---- last block: fp64 reduction of 1036 partials (reuse stage smem) ----
    double a0 = 0.0, a1 = 0.0, a2 = 0.0, a3 = 0.0;
    for (int i = tid; i < GRID; i += BLK) {
        const float4 v = __ldcg(&g_part[i]);
        a0 += (double)v.x; a1 += (double)v.y;
        a2 += (double)v.z; a3 += (double)v.w;
    }
    double* s0 = (double*)stagebuf;   // staging smem is dead; 2 KB reuse
    double* s1 = s0 + BLK;
    double* s2 = s1 + BLK;
    double* s3 = s2 + BLK;
    s0[tid] = a0; s1[tid] = a1; s2[tid] = a2; s3[tid] = a3;
    __syncthreads();
    #pragma unroll
    for (int o = BLK / 2; o > 0; o >>= 1) {
        if (tid < o) {
            s0[tid] += s0[tid + o]; s1[tid] += s1[tid + o];
            s2[tid] += s2[tid + o]; s3[tid] += s3[tid + o];
        }
        __syncthreads();
    }
    if (tid == 0) {
        const float cls = (float)(5.0 * s0[0]);   // lambda_coord
        const float cnf = (float)(5.0 * s1[0]);
        const float cwh = (float)(5.0 * s2[0]);
        const float nob = (float)(0.5 * s3[0]);   // lambda_noobj
        out[0] = cls;
        out[1] = cnf;
        out[2] = cwh;
        out[3] = nob + cls + cnf + cwh;           // total
        g_count = 0;                              // reset for next graph replay
    }
}

extern "C" void kernel_launch(void* const* d_in, const int* in_sizes, int n_in,
                              void* d_out, int out_size)
{
    const float* P = (const float*)d_in[0];   // predictions [B,S,S,30] fp32
    const float* T = (const float*)d_in[1];   // targets     [B,S,S,30] fp32
    float* out = (float*)d_out;               // [cls, conf, center+wh, total]

    yolo_fused<<<GRID, BLK>>>(P, T, out);
}

// round 14
// speedup vs baseline: 1.1602x; 1.0056x over previous
#include <cuda_runtime.h>
#include <cuda_bf16.h>
#include <cstdint>

// YOLOv1 loss — traffic-reduced: stream T fully (smem, cp.async double-buffer),
// but read ONLY p[0..9] of P (2 sectors/cell) + predicated p[kcol] gather for
// obj cells. Skips P's 20 class channels (~41MB of DRAM traffic, -21%).
// BLK=128, TILE=128, 6 blocks/SM (24 warps), persistent grid-stride.

#define NCELL  (16384 * 7 * 7)       // 802816
#define BLK    128
#define BPSM   6
#define GRID   (148 * BPSM)          // 888 persistent blocks
#define TILE   128                   // cells per tile
#define NTILE  (NCELL / TILE)        // 6272
#define TFL    (TILE * 30)           // floats per tensor per tile (3840)
#define TF4    (TFL / 4)             // float4 per T tile (960)

__device__ float4 g_part[GRID];
__device__ unsigned int g_count = 0;

__device__ __forceinline__ void cp16(float4* dst_smem, const float4* src_gmem) {
    unsigned int d = (unsigned int)__cvta_generic_to_shared(dst_smem);
    asm volatile("cp.async.cg.shared.global [%0], [%1], 16;\n" :: "r"(d), "l"(src_gmem));
}
__device__ __forceinline__ void cp_commit() { asm volatile("cp.async.commit_group;\n"); }
__device__ __forceinline__ void cp_wait1()  { asm volatile("cp.async.wait_group 1;\n"); }

__device__ __forceinline__ void prefetch_T(float* stage, int tile,
                                           const float* T, int tid)
{
    const float4* gt = (const float4*)(T + (size_t)tile * TFL);
    float4* d = (float4*)stage;
    #pragma unroll
    for (int i = 0; i < 8; ++i) {
        const int idx = tid + i * BLK;            // 0..1023
        if (idx < TF4) cp16(d + idx, gt + idx);
    }
}

// per-thread: p[0..9] of this thread's own cell, 5x LDG.64 (8B-aligned, 2 sectors)
__device__ __forceinline__ void loadP10(float2* w, const float* P, int cell)
{
    const float2* gp = (const float2*)(P + (size_t)cell * 30);
    #pragma unroll
    for (int j = 0; j < 5; ++j) w[j] = __ldg(gp + j);
}

__global__ __launch_bounds__(BLK, BPSM)
void yolo_fused(const float* __restrict__ P,
                const float* __restrict__ T,
                float* __restrict__ out)
{
    __shared__ float stagebuf[2 * TFL];     // 2 T-stages x 15360 B = 30720 B
    const int tid = threadIdx.x;
    const float CELL = 1.0f / 7.0f;

    float ax = 0.0f, ay = 0.0f, az = 0.0f, aw = 0.0f;

    float2 w[5];                  // current tile: p[0..9]
    float2 nw[5];                 // landing zone: next tile's p[0..9]

    const int t0i = blockIdx.x;
    int s = 0;
    prefetch_T(stagebuf, t0i, T, tid);      // t0i < NTILE always
    cp_commit();
    loadP10(w, P, t0i * TILE + tid);

    for (int tile = t0i; tile < NTILE; tile += GRID) {
        const int nx = tile + GRID;
        if (nx < NTILE) prefetch_T(stagebuf + (s ^ 1) * TFL, nx, T, tid);
        cp_commit();                         // (possibly empty) group
        if (nx < NTILE) loadP10(nw, P, nx * TILE + tid);   // overlaps compute
        cp_wait1();                          // current T stage complete
        __syncthreads();

        const float* t = stagebuf + s * TFL + tid * 30;

        // ---- argmax over t[10:30] FIRST so the gather issues early ----
        float av[10]; int ak[10];
        #pragma unroll
        for (int k = 0; k < 10; ++k) {
            const float a = t[10 + 2 * k], b = t[11 + 2 * k];
            const bool g = b > a;
            av[k] = g ? b : a;
            ak[k] = 10 + 2 * k + (g ? 1 : 0);
        }
        #pragma unroll
        for (int k = 0; k < 5; ++k) {
            const bool g = av[2 * k + 1] > av[2 * k];
            av[k] = g ? av[2 * k + 1] : av[2 * k];
            ak[k] = g ? ak[2 * k + 1] : ak[2 * k];
        }
        { const bool g = av[1] > av[0]; av[0] = g ? av[1] : av[0]; ak[0] = g ? ak[1] : ak[0]; }
        { const bool g = av[3] > av[2]; av[2] = g ? av[3] : av[2]; ak[2] = g ? ak[3] : ak[2]; }
        { const bool g = av[2] > av[0]; av[0] = g ? av[2] : av[0]; ak[0] = g ? ak[2] : ak[0]; }
        { const bool g = av[4] > av[0]; av[0] = g ? av[4] : av[0]; ak[0] = g ? ak[4] : ak[0]; }
        const int   kcol = ak[0];
        const float tmax = av[0];           // == t[kcol]

        const float tc = t[4];
        const bool obj = (tc == 1.0f);
        const bool noo = (tc == 0.0f);

        // predicated gather: only obj cells read p[kcol] (25%)
        float pk = 0.0f;
        if (obj) pk = __ldg(P + (size_t)(tile * TILE + tid) * 30 + kcol);

        const float t0 = t[0], t1 = t[1], t2 = t[2], t3 = t[3];

        // target corners — faithful to the reference's in-place bug:
        //   xy1 = xy*CELL - wh*0.5 ;  xy2 = xy1*CELL + wh*0.5
        const float twx = t2 * t2, twy = t3 * t3;
        const float tx1 = t0 * CELL - 0.5f * twx;
        const float ty1 = t1 * CELL - 0.5f * twy;
        const float tx2 = tx1 * CELL + 0.5f * twx;
        const float ty2 = ty1 * CELL + 0.5f * twy;
        const float area_t = (tx2 - tx1) * (ty2 - ty1);

        // predicted boxes from registers: w0={p0,p1} w1={p2,p3} w2={p4,p5}
        //                                 w3={p6,p7} w4={p8,p9}
        float iou0, iou1;
        {
            const float pwx = w[1].x * w[1].x, pwy = w[1].y * w[1].y;
            const float x1 = w[0].x * CELL - 0.5f * pwx;
            const float y1 = w[0].y * CELL - 0.5f * pwy;
            const float x2 = x1 * CELL + 0.5f * pwx;
            const float y2 = y1 * CELL + 0.5f * pwy;
            const float dx = fmaxf(fminf(x2, tx2) - fmaxf(x1, tx1), 0.0f);
            const float dy = fmaxf(fminf(y2, ty2) - fmaxf(y1, ty1), 0.0f);
            const float inter = dx * dy;
            const float area_p = (x2 - x1) * (y2 - y1);
            iou0 = inter / (area_p + area_t - inter);
        }
        {
            const float pwx = w[3].y * w[3].y, pwy = w[4].x * w[4].x;
            const float x1 = w[2].y * CELL - 0.5f * pwx;
            const float y1 = w[3].x * CELL - 0.5f * pwy;
            const float x2 = x1 * CELL + 0.5f * pwx;
            const float y2 = y1 * CELL + 0.5f * pwy;
            const float dx = fmaxf(fminf(x2, tx2) - fmaxf(x1, tx1), 0.0f);
            const float dy = fmaxf(fminf(y2, ty2) - fmaxf(y1, ty1), 0.0f);
            const float inter = dx * dy;
            const float area_p = (x2 - x1) * (y2 - y1);
            iou1 = inter / (area_p + area_t - inter);
        }
        const bool b1 = (iou1 > iou0);      // first max wins ties

        // responsible-box P values via register selects (no indexed access)
        const float q0 = b1 ? w[2].y : w[0].x;   // p[5] : p[0]
        const float q1 = b1 ? w[3].x : w[0].y;   // p[6] : p[1]
        const float q2 = b1 ? w[3].y : w[1].x;   // p[7] : p[2]
        const float q3 = b1 ? w[4].x : w[1].y;   // p[8] : p[3]
        const float q4 = b1 ? w[4].y : w[2].x;   // p[9] : p[4]
        const int   b5 = b1 ? 5 : 0;

        const float dk = pk - tmax;
        const float dc = q4 - t[b5 + 4];
        const float d0 = q0 - t[b5 + 0];
        const float d1 = q1 - t[b5 + 1];
        const float d2 = q2 - t[b5 + 2];
        const float d3 = q3 - t[b5 + 3];
        const float d4 = w[2].x - tc;            // p[4] - t[4]
        const float d9 = w[4].y - t[9];          // p[9] - t[9]

        if (obj) {
            ax += dk * dk;                                   // cls
            ay += dc * dc;                                   // conf
            az += d0 * d0 + d1 * d1 + d2 * d2 + d3 * d3;     // center+wh
        }
        if (noo) aw += d4 * d4 + d9 * d9;                    // noobj

        __syncthreads();              // reads done before stage s is reused
        s ^= 1;
        if (nx < NTILE) {
            #pragma unroll
            for (int j = 0; j < 5; ++j) w[j] = nw[j];
        }
    }

    // ---- block reduce ----
    #pragma unroll
    for (int o = 16; o > 0; o >>= 1) {
        ax += __shfl_down_sync(0xffffffffu, ax, o);
        ay += __shfl_down_sync(0xffffffffu, ay, o);
        az += __shfl_down_sync(0xffffffffu, az, o);
        aw += __shfl_down_sync(0xffffffffu, aw, o);
    }
    __shared__ float4 wsum[BLK / 32];
    __shared__ bool s_last;
    if ((tid & 31) == 0) wsum[tid >> 5] = make_float4(ax, ay, az, aw);
    __syncthreads();
    if (tid == 0) {
        float4 sv = wsum[0];
        #pragma unroll
        for (int wv = 1; wv < BLK / 32; ++wv) {
            sv.x += wsum[wv].x; sv.y += wsum[wv].y;
            sv.z += wsum[wv].z; sv.w += wsum[wv].w;
        }
        __stcg(&g_part[blockIdx.x], sv);
        __threadfence();
        unsigned int prev = atomicAdd(&g_count, 1u);
        s_last = (prev == (unsigned int)(GRID - 1));
    }
    __syncthreads();
    if (!s_last) return;

    // ---- last block: fp64 reduction of 888 partials (reuse stage smem) ----
    double a0 = 0.0, a1 = 0.0, a2 = 0.0, a3 = 0.0;
    for (int i = tid; i < GRID; i += BLK) {
        const float4 v = __ldcg(&g_part[i]);
        a0 += (double)v.x; a1 += (double)v.y;
        a2 += (double)v.z; a3 += (double)v.w;
    }
    double* s0 = (double*)stagebuf;   // staging smem is dead; 4 KB reuse
    double* s1 = s0 + BLK;
    double* s2 = s1 + BLK;
    double* s3 = s2 + BLK;
    s0[tid] = a0; s1[tid] = a1; s2[tid] = a2; s3[tid] = a3;
    __syncthreads();
    #pragma unroll
    for (int o = BLK / 2; o > 0; o >>= 1) {
        if (tid < o) {
            s0[tid] += s0[tid + o]; s1[tid] += s1[tid + o];
            s2[tid] += s2[tid + o]; s3[tid] += s3[tid + o];
        }
        __syncthreads();
    }
    if (tid == 0) {
        const float cls = (float)(5.0 * s0[0]);   // lambda_coord
        const float cnf = (float)(5.0 * s1[0]);
        const float cwh = (float)(5.0 * s2[0]);
        const float nob = (float)(0.5 * s3[0]);   // lambda_noobj
        out[0] = cls;
        out[1] = cnf;
        out[2] = cwh;
        out[3] = nob + cls + cnf + cwh;           // total
        g_count = 0;                              // reset for next graph replay
    }
}

extern "C" void kernel_launch(void* const* d_in, const int* in_sizes, int n_in,
                              void* d_out, int out_size)
{
    const float* P = (const float*)d_in[0];   // predictions [B,S,S,30] fp32
    const float* T = (const float*)d_in[1];   // targets     [B,S,S,30] fp32
    float* out = (float*)d_out;               // [cls, conf, center+wh, total]

    yolo_fused<<<GRID, BLK>>>(P, T, out);
}

// round 15
// speedup vs baseline: 1.2671x; 1.0921x over previous
#include <cuda_runtime.h>
#include <cuda_bf16.h>
#include <cstdint>

// YOLOv1 loss — half-tile double-buffered cp.async at FULL occupancy:
// BLK=128, stage = 64 cells (15.36KB), 2 stages = 30.72KB -> 7 blocks/SM
// (28 warps) AND continuous demand (next stage always in flight).
// All threads stage; threads 0-63 compute. R8's proven last-block epilogue.

#define NCELL  (16384 * 7 * 7)       // 802816
#define BLK    128
#define BPSM   7
#define GRID   (148 * BPSM)          // 1036 persistent blocks
#define HT     64                    // cells per half-tile
#define NHT    (NCELL / HT)          // 12544 half-tiles
#define HFL    (HT * 30)             // floats per tensor per half-tile (1920)
#define HF4    (HFL / 4)             // float4 per tensor (480)
#define STGF   (2 * HFL)             // floats per stage [P|T] (3840)

__device__ float4 g_part[GRID];
__device__ unsigned int g_count = 0;

__device__ __forceinline__ void cp16(float4* dst_smem, const float4* src_gmem) {
    unsigned int d = (unsigned int)__cvta_generic_to_shared(dst_smem);
    asm volatile("cp.async.cg.shared.global [%0], [%1], 16;\n" :: "r"(d), "l"(src_gmem));
}
__device__ __forceinline__ void cp_commit() { asm volatile("cp.async.commit_group;\n"); }
__device__ __forceinline__ void cp_wait1()  { asm volatile("cp.async.wait_group 1;\n"); }

__device__ __forceinline__ void prefetch_ht(float* stage, int ht,
                                            const float* P, const float* T, int tid)
{
    const float4* gp = (const float4*)(P + (size_t)ht * HFL);
    const float4* gt = (const float4*)(T + (size_t)ht * HFL);
    float4* d = (float4*)stage;
    #pragma unroll
    for (int i = 0; i < 8; ++i) {
        const int idx = tid + i * BLK;            // 0..1023
        if (idx < 2 * HF4) {                      // 960 float4 total
            const float4* src = (idx < HF4) ? (gp + idx) : (gt + (idx - HF4));
            cp16(d + idx, src);
        }
    }
}

__global__ __launch_bounds__(BLK, BPSM)
void yolo_fused(const float* __restrict__ P,
                const float* __restrict__ T,
                float* __restrict__ out)
{
    __shared__ float stagebuf[2 * STGF];    // 2 stages x 15360 B = 30720 B
    const int tid = threadIdx.x;
    const float CELL = 1.0f / 7.0f;

    float ax = 0.0f, ay = 0.0f, az = 0.0f, aw = 0.0f;

    int s = 0;
    prefetch_ht(stagebuf, blockIdx.x, P, T, tid);   // blockIdx.x < NHT always
    cp_commit();

    for (int ht = blockIdx.x; ht < NHT; ht += GRID) {
        const int nx = ht + GRID;
        if (nx < NHT) prefetch_ht(stagebuf + (s ^ 1) * STGF, nx, P, T, tid);
        cp_commit();                          // (possibly empty) group
        cp_wait1();                           // current stage complete
        __syncthreads();

        if (tid < HT) {
            const float* p = stagebuf + s * STGF + tid * 30;
            const float* t = p + HFL;

            const float t0 = t[0], t1 = t[1], t2 = t[2], t3 = t[3], tc = t[4];

            // target corners — faithful to the reference's in-place bug:
            //   xy1 = xy*CELL - wh*0.5 ;  xy2 = xy1*CELL + wh*0.5
            const float twx = t2 * t2, twy = t3 * t3;
            const float tx1 = t0 * CELL - 0.5f * twx;
            const float ty1 = t1 * CELL - 0.5f * twy;
            const float tx2 = tx1 * CELL + 0.5f * twx;
            const float ty2 = ty1 * CELL + 0.5f * twy;
            const float area_t = (tx2 - tx1) * (ty2 - ty1);

            float iou0, iou1;
            #pragma unroll
            for (int b = 0; b < 2; ++b) {
                const float px = p[b * 5 + 0], py = p[b * 5 + 1];
                const float pw = p[b * 5 + 2], ph = p[b * 5 + 3];
                const float pwx = pw * pw, pwy = ph * ph;
                const float x1 = px * CELL - 0.5f * pwx;
                const float y1 = py * CELL - 0.5f * pwy;
                const float x2 = x1 * CELL + 0.5f * pwx;
                const float y2 = y1 * CELL + 0.5f * pwy;
                const float ltx = fmaxf(x1, tx1), lty = fmaxf(y1, ty1);
                const float rbx = fminf(x2, tx2), rby = fminf(y2, ty2);
                const float dx = fmaxf(rbx - ltx, 0.0f);
                const float dy = fmaxf(rby - lty, 0.0f);
                const float inter  = dx * dy;
                const float area_p = (x2 - x1) * (y2 - y1);
                const float v = inter / (area_p + area_t - inter);
                if (b == 0) iou0 = v; else iou1 = v;
            }
            const int b5 = (iou1 > iou0) ? 5 : 0;     // first max wins ties

            // argmax over t[10:30] — order-preserving tree (exact first-max)
            float av[10]; int ak[10];
            #pragma unroll
            for (int k = 0; k < 10; ++k) {
                const float a = t[10 + 2 * k], b = t[11 + 2 * k];
                const bool g = b > a;
                av[k] = g ? b : a;
                ak[k] = 10 + 2 * k + (g ? 1 : 0);
            }
            #pragma unroll
            for (int k = 0; k < 5; ++k) {
                const bool g = av[2 * k + 1] > av[2 * k];
                av[k] = g ? av[2 * k + 1] : av[2 * k];
                ak[k] = g ? ak[2 * k + 1] : ak[2 * k];
            }
            { const bool g = av[1] > av[0]; av[0] = g ? av[1] : av[0]; ak[0] = g ? ak[1] : ak[0]; }
            { const bool g = av[3] > av[2]; av[2] = g ? av[3] : av[2]; ak[2] = g ? ak[3] : ak[2]; }
            { const bool g = av[2] > av[0]; av[0] = g ? av[2] : av[0]; ak[0] = g ? ak[2] : ak[0]; }
            { const bool g = av[4] > av[0]; av[0] = g ? av[4] : av[0]; ak[0] = g ? ak[4] : ak[0]; }
            const int   kcol = ak[0];
            const float tmax = av[0];     // == t[kcol]

            const bool obj = (tc == 1.0f);
            const bool noo = (tc == 0.0f);

            const float dk = p[kcol]   - tmax;
            const float dc = p[b5 + 4] - t[b5 + 4];
            const float d0 = p[b5 + 0] - t[b5 + 0];
            const float d1 = p[b5 + 1] - t[b5 + 1];
            const float d2 = p[b5 + 2] - t[b5 + 2];
            const float d3 = p[b5 + 3] - t[b5 + 3];
            const float d4 = p[4] - tc;
            const float d9 = p[9] - t[9];

            if (obj) {
                ax += dk * dk;                                   // cls
                ay += dc * dc;                                   // conf
                az += d0 * d0 + d1 * d1 + d2 * d2 + d3 * d3;     // center+wh
            }
            if (noo) aw += d4 * d4 + d9 * d9;                    // noobj
        }

        __syncthreads();              // reads done before stage s is reused
        s ^= 1;
    }

    // ---- block reduce ----
    #pragma unroll
    for (int o = 16; o > 0; o >>= 1) {
        ax += __shfl_down_sync(0xffffffffu, ax, o);
        ay += __shfl_down_sync(0xffffffffu, ay, o);
        az += __shfl_down_sync(0xffffffffu, az, o);
        aw += __shfl_down_sync(0xffffffffu, aw, o);
    }
    __shared__ float4 wsum[BLK / 32];
    __shared__ bool s_last;
    if ((tid & 31) == 0) wsum[tid >> 5] = make_float4(ax, ay, az, aw);
    __syncthreads();
    if (tid == 0) {
        float4 sv = wsum[0];
        #pragma unroll
        for (int w = 1; w < BLK / 32; ++w) {
            sv.x += wsum[w].x; sv.y += wsum[w].y;
            sv.z += wsum[w].z; sv.w += wsum[w].w;
        }
        __stcg(&g_part[blockIdx.x], sv);
        __threadfence();
        unsigned int prev = atomicAdd(&g_count, 1u);
        s_last = (prev == (unsigned int)(GRID - 1));
    }
    __syncthreads();
    if (!s_last) return;

    // ---- last block: fp64 reduction of 1036 partials (reuse stage smem) ----
    double a0 = 0.0, a1 = 0.0, a2 = 0.0, a3 = 0.0;
    for (int i = tid; i < GRID; i += BLK) {
        const float4 v = __ldcg(&g_part[i]);
        a0 += (double)v.x; a1 += (double)v.y;
        a2 += (double)v.z; a3 += (double)v.w;
    }
    double* s0 = (double*)stagebuf;   // staging smem is dead; 4 KB reuse
    double* s1 = s0 + BLK;
    double* s2 = s1 + BLK;
    double* s3 = s2 + BLK;
    s0[tid] = a0; s1[tid] = a1; s2[tid] = a2; s3[tid] = a3;
    __syncthreads();
    #pragma unroll
    for (int o = BLK / 2; o > 0; o >>= 1) {
        if (tid < o) {
            s0[tid] += s0[tid + o]; s1[tid] += s1[tid + o];
            s2[tid] += s2[tid + o]; s3[tid] += s3[tid + o];
        }
        __syncthreads();
    }
    if (tid == 0) {
        const float cls = (float)(5.0 * s0[0]);   // lambda_coord
        const float cnf = (float)(5.0 * s1[0]);
        const float cwh = (float)(5.0 * s2[0]);
        const float nob = (float)(0.5 * s3[0]);   // lambda_noobj
        out[0] = cls;
        out[1] = cnf;
        out[2] = cwh;
        out[3] = nob + cls + cnf + cwh;           // total
        g_count = 0;                              // reset for next graph replay
    }
}

extern "C" void kernel_launch(void* const* d_in, const int* in_sizes, int n_in,
                              void* d_out, int out_size)
{
    const float* P = (const float*)d_in[0];   // predictions [B,S,S,30] fp32
    const float* T = (const float*)d_in[1];   // targets     [B,S,S,30] fp32
    float* out = (float*)d_out;               // [cls, conf, center+wh, total]

    yolo_fused<<<GRID, BLK>>>(P, T, out);
}